// round 1
// baseline (speedup 1.0000x reference)
#include <cuda_runtime.h>

// Problem constants (fixed by the dataset)
#define NN 50000
#define EE 1600000
#define DD 64
#define HH 32
#define NEG_SLOPE 0.2f

#define NB_SCAN 49  // ceil(50000/1024)

// ---------------- scratch (static device globals; no allocation allowed) ----
__device__ float d_xl[NN * HH];
__device__ float d_xr[NN * HH];
__device__ float d_hbuf[NN * HH];
__device__ int d_deg[NN];
__device__ int d_rowoff[NN + 1];
__device__ int d_cursor[NN];
__device__ int d_esrc[EE];
__device__ int d_bsum[64];

// ---------------- CSR build ----------------

__global__ void zero_deg_kernel() {
    int i = blockIdx.x * blockDim.x + threadIdx.x;
    if (i < NN) d_deg[i] = 0;
}

__global__ void hist_kernel(const int* __restrict__ dst) {
    int e = blockIdx.x * blockDim.x + threadIdx.x;
    if (e < EE) atomicAdd(&d_deg[dst[e]], 1);
}

// per-block exclusive scan of d_deg -> d_rowoff (block-local), block totals -> d_bsum
__global__ void scan1_kernel() {
    __shared__ int warp_sums[32];
    int i = blockIdx.x * 1024 + threadIdx.x;
    int v = (i < NN) ? d_deg[i] : 0;
    int x = v;
    int lane = threadIdx.x & 31;
    int wid = threadIdx.x >> 5;
#pragma unroll
    for (int o = 1; o < 32; o <<= 1) {
        int y = __shfl_up_sync(0xffffffffu, x, o);
        if (lane >= o) x += y;
    }
    if (lane == 31) warp_sums[wid] = x;
    __syncthreads();
    if (wid == 0) {
        int w = warp_sums[lane];
#pragma unroll
        for (int o = 1; o < 32; o <<= 1) {
            int y = __shfl_up_sync(0xffffffffu, w, o);
            if (lane >= o) w += y;
        }
        warp_sums[lane] = w;
    }
    __syncthreads();
    int blockpref = (wid > 0) ? warp_sums[wid - 1] : 0;
    int incl = x + blockpref;
    if (i < NN) d_rowoff[i] = incl - v;  // exclusive within block
    if (threadIdx.x == 1023) d_bsum[blockIdx.x] = incl;
}

__global__ void scan2_kernel() {
    // tiny: exclusive scan of 49 block sums, single thread
    if (threadIdx.x == 0 && blockIdx.x == 0) {
        int run = 0;
        for (int b = 0; b < NB_SCAN; b++) {
            int t = d_bsum[b];
            d_bsum[b] = run;
            run += t;
        }
    }
}

__global__ void scan3_kernel() {
    int i = blockIdx.x * 1024 + threadIdx.x;
    if (i < NN) {
        int r = d_rowoff[i] + d_bsum[blockIdx.x];
        d_rowoff[i] = r;
        d_cursor[i] = r;
    }
    if (i == 0) d_rowoff[NN] = EE;
}

__global__ void scatter_kernel(const int* __restrict__ src, const int* __restrict__ dst) {
    int e = blockIdx.x * blockDim.x + threadIdx.x;
    if (e < EE) {
        int d = dst[e];
        int p = atomicAdd(&d_cursor[d], 1);
        d_esrc[p] = src[e];
    }
}

// ---------------- projections: xl = x @ Wl, xr = x @ Wr ----------------
// Thread-per-node; W broadcast from shared memory (conflict-free broadcast).
template <int DIN>
__global__ void proj_kernel(const float* __restrict__ x,
                            const float* __restrict__ Wl,
                            const float* __restrict__ Wr,
                            float* __restrict__ xl, float* __restrict__ xr) {
    __shared__ float2 sWl[DIN * 16];
    __shared__ float2 sWr[DIN * 16];
    for (int t = threadIdx.x; t < DIN * 16; t += blockDim.x) {
        sWl[t] = ((const float2*)Wl)[t];
        sWr[t] = ((const float2*)Wr)[t];
    }
    __syncthreads();
    int i = blockIdx.x * blockDim.x + threadIdx.x;
    if (i >= NN) return;

    float2 accl[16], accr[16];
#pragma unroll
    for (int c = 0; c < 16; c++) {
        accl[c] = make_float2(0.f, 0.f);
        accr[c] = make_float2(0.f, 0.f);
    }
    const float4* xrow = (const float4*)(x + (size_t)i * DIN);
#pragma unroll 2
    for (int k4 = 0; k4 < DIN / 4; k4++) {
        float4 xv = xrow[k4];
        float xs[4] = {xv.x, xv.y, xv.z, xv.w};
#pragma unroll
        for (int q = 0; q < 4; q++) {
            int k = k4 * 4 + q;
            float xk = xs[q];
#pragma unroll
            for (int c = 0; c < 16; c++) {
                float2 w = sWl[k * 16 + c];
                accl[c].x += xk * w.x;
                accl[c].y += xk * w.y;
                float2 w2 = sWr[k * 16 + c];
                accr[c].x += xk * w2.x;
                accr[c].y += xk * w2.y;
            }
        }
    }
    float2* ol = (float2*)(xl + (size_t)i * HH);
    float2* orr = (float2*)(xr + (size_t)i * HH);
#pragma unroll
    for (int c = 0; c < 16; c++) {
        ol[c] = accl[c];
        orr[c] = accr[c];
    }
}

// ---------------- GATv2 edge layer: warp per node, lane = channel -----------
// Online softmax: out_i = (sum_j exp(e_j - m) * xl_j) / (sum_j exp(e_j - m)) + b
__global__ void gat_layer_kernel(const float* __restrict__ xl,
                                 const float* __restrict__ xr,
                                 const float* __restrict__ att,
                                 const float* __restrict__ bias,
                                 float* __restrict__ out, int do_relu) {
    int warp = (blockIdx.x * blockDim.x + threadIdx.x) >> 5;
    if (warp >= NN) return;
    int lane = threadIdx.x & 31;

    float att_c = att[lane];
    float xr_c = xr[warp * HH + lane];
    int row = d_rowoff[warp];
    int end = d_rowoff[warp + 1];

    float m = -1e30f;
    float denom = 0.f;
    float acc = 0.f;

    for (int base = row; base < end; base += 32) {
        int nj = min(32, end - base);
        int sj = (base + lane < end) ? d_esrc[base + lane] : 0;
        for (int j = 0; j < nj; j++) {
            int s = __shfl_sync(0xffffffffu, sj, j);
            float v = __ldg(&xl[s * HH + lane]);
            float t = v + xr_c;
            float lr = (t > 0.f) ? t : NEG_SLOPE * t;
            float c = lr * att_c;
            // butterfly all-reduce -> e on every lane
            c += __shfl_xor_sync(0xffffffffu, c, 16);
            c += __shfl_xor_sync(0xffffffffu, c, 8);
            c += __shfl_xor_sync(0xffffffffu, c, 4);
            c += __shfl_xor_sync(0xffffffffu, c, 2);
            c += __shfl_xor_sync(0xffffffffu, c, 1);
            float e = c;
            if (e > m) {  // warp-uniform branch
                float sc = __expf(m - e);
                denom *= sc;
                acc *= sc;
                m = e;
            }
            float p = __expf(e - m);
            denom += p;
            acc += p * v;
        }
    }

    float res;
    if (end > row)
        res = acc / denom + bias[lane];
    else
        res = bias[lane];  // empty segment: reference yields bias
    if (do_relu) res = fmaxf(res, 0.f);
    out[warp * HH + lane] = res;
}

// ---------------- launch ----------------
extern "C" void kernel_launch(void* const* d_in, const int* in_sizes, int n_in,
                              void* d_out, int out_size) {
    const float* x = (const float*)d_in[0];
    const int* ei = (const int*)d_in[1];
    const float* Wl1 = (const float*)d_in[2];
    const float* Wr1 = (const float*)d_in[3];
    const float* att1 = (const float*)d_in[4];
    const float* b1 = (const float*)d_in[5];
    const float* Wl2 = (const float*)d_in[6];
    const float* Wr2 = (const float*)d_in[7];
    const float* att2 = (const float*)d_in[8];
    const float* b2 = (const float*)d_in[9];
    float* out = (float*)d_out;

    const int* src = ei;
    const int* dst = ei + EE;

    float* xl;
    float* xr;
    float* hbuf;
    cudaGetSymbolAddress((void**)&xl, d_xl);
    cudaGetSymbolAddress((void**)&xr, d_xr);
    cudaGetSymbolAddress((void**)&hbuf, d_hbuf);

    // CSR build
    zero_deg_kernel<<<(NN + 255) / 256, 256>>>();
    hist_kernel<<<(EE + 255) / 256, 256>>>(dst);
    scan1_kernel<<<NB_SCAN, 1024>>>();
    scan2_kernel<<<1, 32>>>();
    scan3_kernel<<<NB_SCAN, 1024>>>();
    scatter_kernel<<<(EE + 255) / 256, 256>>>(src, dst);

    // Layer 1
    proj_kernel<DD><<<(NN + 255) / 256, 256>>>(x, Wl1, Wr1, xl, xr);
    gat_layer_kernel<<<(NN + 7) / 8, 256>>>(xl, xr, att1, b1, hbuf, 1);

    // Layer 2
    proj_kernel<HH><<<(NN + 255) / 256, 256>>>(hbuf, Wl2, Wr2, xl, xr);
    gat_layer_kernel<<<(NN + 7) / 8, 256>>>(xl, xr, att2, b2, out, 0);
}